// round 5
// baseline (speedup 1.0000x reference)
#include <cuda_runtime.h>
#include <math.h>

#define BATCH 16384
#define B6 (BATCH*6)
#define H 128
#define DTc 0.01f
#define WARPS 13
#define TPB (WARPS*32)
#define NBLK 152

// ---- shared-memory weight layout (float offsets) ----
// S2L/S2V: k-pair interleaved [k/2][128*2]: (k,m) -> (k>>1)*256 + m*2 + (k&1)
// S3P:     k-pair interleaved [k/2][48]:    (k,o) -> (k>>1)*48 + o*2 + (k&1)
#define OFF_S1L 0        // [12][128]  W1L^T
#define OFF_S2L 1536     // 16384
#define OFF_S3P 17920    // 3072
#define OFF_B1L 20992
#define OFF_B2L 21120
#define OFF_B3L 21248    // 24 slots (21 used)
#define OFF_S1V 21272    // [12][128]  W1V^T
#define OFF_S2V 22808    // 16384
#define OFF_W3V 39192
#define OFF_B1V 39320
#define OFF_B2V 39448
#define WTOT    39576
#define SCR     1280     // per-warp scratch floats
#define SMEM_FLOATS (WTOT + WARPS*SCR)
#define SMEM_BYTES  (SMEM_FLOATS*4)

typedef unsigned long long ull;

__device__ float g_qs[B6];
__device__ float g_qds[B6];
__device__ float g_kqd[4][B6];
__device__ unsigned g_mask[4];

__constant__ float c_LOWER[6]  = {-6.28f,-6.28f,-3.14f,-6.28f,-6.28f,-6.28f};
__constant__ float c_UPPER[6]  = { 6.28f, 6.28f, 3.14f, 6.28f, 6.28f, 6.28f};
__constant__ float c_EFFORT[6] = {150.f,150.f,150.f,28.f,28.f,28.f};
__constant__ int   c_TI[21] = {0,1,1,2,2,2,3,3,3,3,4,4,4,4,4,5,5,5,5,5,5};
__constant__ int   c_TJ[21] = {0,0,1,0,1,2,0,1,2,3,0,1,2,3,4,0,1,2,3,4,5};

// ---- packed fp32x2 helpers ----
__device__ __forceinline__ ull pk2(float a, float b){
    ull r; asm("mov.b64 %0, {%1, %2};" : "=l"(r) : "f"(a), "f"(b)); return r;
}
__device__ __forceinline__ void upk2(ull v, float& a, float& b){
    asm("mov.b64 {%0, %1}, %2;" : "=f"(a), "=f"(b) : "l"(v));
}
__device__ __forceinline__ ull ffma2(ull a, ull b, ull c){
    ull d; asm("fma.rn.f32x2 %0, %1, %2, %3;" : "=l"(d) : "l"(a), "l"(b), "l"(c)); return d;
}
__device__ __forceinline__ float hsum2(ull v){
    float a, b; upk2(v, a, b); return a + b;
}

// fast softplus + sigmoid sharing one exp
__device__ __forceinline__ void spsig(float x, float& sp, float& sg){
    float e = __expf(-fabsf(x));
    float r = __fdividef(1.0f, 1.0f + e);
    sp = fmaxf(x, 0.0f) + __logf(1.0f + e);
    sg = (x >= 0.0f) ? r : (1.0f - r);
}
__device__ __forceinline__ float sig_f(float x){
    float e = __expf(-fabsf(x));
    float r = __fdividef(1.0f, 1.0f + e);
    return (x >= 0.0f) ? r : (1.0f - r);
}
__device__ __forceinline__ float wsum(float v){
    #pragma unroll
    for (int o = 16; o; o >>= 1) v += __shfl_xor_sync(0xffffffffu, v, o);
    return v;
}

// ---------------- mask zeroing ----------------
__global__ void zeroMaskK(){
    if (threadIdx.x < 4) g_mask[threadIdx.x] = 0u;
}

// ---------------- stage state + violation mask ----------------
__global__ void stageAK(const float* __restrict__ obs, int stage){
    int e = blockIdx.x*blockDim.x + threadIdx.x;
    unsigned bits = 0u;
    if (e < BATCH){
        #pragma unroll
        for (int i = 0; i < 6; i++){
            float q  = obs[e*12 + i];
            float qd = obs[e*12 + 6 + i];
            float qs, qds;
            if (stage == 0){
                qs = q; qds = qd;
            } else if (stage == 1){
                float k1 = g_kqd[0][e*6+i];
                qs  = q + 0.5f*DTc*qd;
                qds = qd + 0.5f*DTc*k1;
            } else if (stage == 2){
                float k1 = g_kqd[0][e*6+i];
                float k2 = g_kqd[1][e*6+i];
                float k2q = qd + 0.5f*DTc*k1;
                qs  = q + 0.5f*DTc*k2q;
                qds = qd + 0.5f*DTc*k2;
            } else {
                float k2 = g_kqd[1][e*6+i];
                float k3 = g_kqd[2][e*6+i];
                float k3q = qd + 0.5f*DTc*k2;
                qs  = q + DTc*k3q;
                qds = qd + DTc*k3;
            }
            g_qs[e*6+i]  = qs;
            g_qds[e*6+i] = qds;
            float lo = c_LOWER[i] + 0.1f;
            float up = c_UPPER[i] - 0.1f;
            if (qs <= lo || qs >= up) bits |= (1u << i);
        }
    }
    if (bits) atomicOr(&g_mask[stage], bits);
}

// ---------------- heavy accel kernel ----------------
__global__ void __launch_bounds__(TPB, 1) stageBK(
    const float* __restrict__ W1L, const float* __restrict__ b1L,
    const float* __restrict__ W2L, const float* __restrict__ b2L,
    const float* __restrict__ W3L, const float* __restrict__ b3L,
    const float* __restrict__ W1V, const float* __restrict__ b1V,
    const float* __restrict__ W2V, const float* __restrict__ b2V,
    const float* __restrict__ W3V, const float* __restrict__ action,
    int stage)
{
    extern __shared__ float s[];
    const int tid = threadIdx.x;

    // stage weights into shared
    for (int i = tid; i < 12*H; i += TPB) s[OFF_S1L + (i%12)*H + i/12] = W1L[i];
    for (int i = tid; i < H*H;  i += TPB){
        int m = i / H, k = i % H;
        s[OFF_S2L + (k>>1)*256 + m*2 + (k&1)] = W2L[i];
    }
    for (int i = tid; i < 21*H; i += TPB){
        int o = i / H, k = i % H;
        s[OFF_S3P + (k>>1)*48 + o*2 + (k&1)] = W3L[i];
    }
    for (int i = tid; i < 12*H; i += TPB) s[OFF_S1V + (i%12)*H + i/12] = W1V[i];
    for (int i = tid; i < H*H;  i += TPB){
        int m = i / H, k = i % H;
        s[OFF_S2V + (k>>1)*256 + m*2 + (k&1)] = W2V[i];
    }
    for (int i = tid; i < H; i += TPB){
        s[OFF_B1L+i]=b1L[i]; s[OFF_B2L+i]=b2L[i];
        s[OFF_B1V+i]=b1V[i]; s[OFF_B2V+i]=b2V[i];
        s[OFF_W3V+i]=W3V[i];
    }
    for (int i = tid; i < 21; i += TPB) s[OFF_B3L+i]=b3L[i];
    __syncthreads();

    const unsigned mask = g_mask[stage];
    const int wid = tid >> 5, lane = tid & 31;
    float* scr   = s + WTOT + wid*SCR;
    float* vecs  = scr;
    float* ydy   = scr + 896;
    float* dmj   = scr + 1048;
    float* psm   = scr + 1176;
    float* gsm   = scr + 1200;
    float* rhssm = scr + 1208;
    float* qsh   = scr + 1216;
    float* qdsh  = scr + 1224;
    float* tcsm  = scr + 1232;
    float* tssm  = scr + 1240;
    const int o0 = lane*4;
    float* kout = g_kqd[stage];

    for (int e = blockIdx.x*WARPS + wid; e < BATCH; e += gridDim.x*WARPS){
        if (lane < 6){
            float qv  = g_qs[e*6+lane];
            float qdv = g_qds[e*6+lane];
            qsh[lane]  = qv;
            qdsh[lane] = qdv;
            float sn, cs;
            __sincosf(qv, &sn, &cs);
            tcsm[lane] = cs;
            tssm[lane] = sn;
        }
        __syncwarp();
        float tc[6], tsn[6], qdr[6];
        #pragma unroll
        for (int i = 0; i < 6; i++){ tc[i]=tcsm[i]; tsn[i]=tssm[i]; qdr[i]=qdsh[i]; }

        // ==================== L network ====================
        // ---- layer 1: h1 + 6 tangents (block m-ownership o0..o0+3)
        {
            float zz[4];
            #pragma unroll
            for (int m=0;m<4;m++) zz[m] = s[OFF_B1L+o0+m];
            #pragma unroll
            for (int k=0;k<12;k++){
                float tk = (k&1) ? tsn[k>>1] : tc[k>>1];
                float4 w = *(const float4*)&s[OFF_S1L + k*H + o0];
                zz[0]+=w.x*tk; zz[1]+=w.y*tk; zz[2]+=w.z*tk; zz[3]+=w.w*tk;
            }
            float s1[4];
            #pragma unroll
            for (int m=0;m<4;m++){
                float spv, sgv; spsig(zz[m], spv, sgv);
                vecs[o0+m] = spv; s1[m] = sgv;
            }
            #pragma unroll
            for (int j=0;j<6;j++){
                float4 wa = *(const float4*)&s[OFF_S1L + (2*j  )*H + o0];
                float4 wb = *(const float4*)&s[OFF_S1L + (2*j+1)*H + o0];
                float cj = tc[j], sj = tsn[j];
                vecs[(j+1)*H + o0 + 0] = s1[0]*(wb.x*cj - wa.x*sj);
                vecs[(j+1)*H + o0 + 1] = s1[1]*(wb.y*cj - wa.y*sj);
                vecs[(j+1)*H + o0 + 2] = s1[2]*(wb.z*cj - wa.z*sj);
                vecs[(j+1)*H + o0 + 3] = s1[3]*(wb.w*cj - wa.w*sj);
            }
        }
        __syncwarp();

        // ---- layer 2, fused over 7 vectors; k-pair packed, strided m-ownership
        {
            ull acc[7][4];
            #pragma unroll
            for (int t=0;t<4;t++) acc[0][t] = pk2(s[OFF_B2L + lane + 32*t], 0.0f);
            #pragma unroll
            for (int v=1;v<7;v++){
                #pragma unroll
                for (int t=0;t<4;t++) acc[v][t] = 0ull;
            }
            for (int k=0;k<H;k+=4){
                ulonglong2 hv[7];
                #pragma unroll
                for (int v=0;v<7;v++) hv[v] = *(const ulonglong2*)&vecs[v*H + k];
                #pragma unroll
                for (int p=0;p<2;p++){
                    const float* wrow = &s[OFF_S2L + ((k>>1)+p)*256];
                    ull wt[4];
                    #pragma unroll
                    for (int t=0;t<4;t++) wt[t] = *(const ull*)&wrow[(lane+32*t)*2];
                    #pragma unroll
                    for (int v=0;v<7;v++){
                        ull hp = p ? hv[v].y : hv[v].x;
                        #pragma unroll
                        for (int t=0;t<4;t++) acc[v][t] = ffma2(wt[t], hp, acc[v][t]);
                    }
                }
            }
            __syncwarp();
            float s2v[4];
            #pragma unroll
            for (int t=0;t<4;t++){
                float spv, sgv; spsig(hsum2(acc[0][t]), spv, sgv);
                vecs[lane+32*t] = spv; s2v[t] = sgv;
            }
            #pragma unroll
            for (int v=1;v<7;v++){
                #pragma unroll
                for (int t=0;t<4;t++) vecs[v*H + lane+32*t] = s2v[t]*hsum2(acc[v][t]);
            }
        }
        __syncwarp();

        // ---- layer 3 (21 outputs), k-pair packed
        if (lane < 21){
            ull facc[7];
            facc[0] = pk2(s[OFF_B3L+lane], 0.0f);
            #pragma unroll
            for (int v=1;v<7;v++) facc[v] = 0ull;
            for (int k=0;k<H;k+=4){
                ulonglong2 hv[7];
                #pragma unroll
                for (int v=0;v<7;v++) hv[v] = *(const ulonglong2*)&vecs[v*H + k];
                #pragma unroll
                for (int p=0;p<2;p++){
                    ull wp = *(const ull*)&s[OFF_S3P + ((k>>1)+p)*48 + lane*2];
                    #pragma unroll
                    for (int v=0;v<7;v++)
                        facc[v] = ffma2(wp, p ? hv[v].y : hv[v].x, facc[v]);
                }
            }
            float spv, s3; spsig(hsum2(facc[0]), spv, s3);
            ydy[lane] = spv;
            #pragma unroll
            for (int v=1;v<7;v++) ydy[v*21+lane] = s3*hsum2(facc[v]);
        }
        __syncwarp();

        // ==================== V network (forward-mode gradient) ====================
        // ---- layer 1: value + 6 tangents (overwrite vecs)
        {
            float zz[4];
            #pragma unroll
            for (int m=0;m<4;m++) zz[m] = s[OFF_B1V+o0+m];
            #pragma unroll
            for (int k=0;k<12;k++){
                float tk = (k&1) ? tsn[k>>1] : tc[k>>1];
                float4 w = *(const float4*)&s[OFF_S1V + k*H + o0];
                zz[0]+=w.x*tk; zz[1]+=w.y*tk; zz[2]+=w.z*tk; zz[3]+=w.w*tk;
            }
            float s1[4];
            #pragma unroll
            for (int m=0;m<4;m++){
                float spv, sgv; spsig(zz[m], spv, sgv);
                vecs[o0+m] = spv; s1[m] = sgv;
            }
            #pragma unroll
            for (int j=0;j<6;j++){
                float4 wa = *(const float4*)&s[OFF_S1V + (2*j  )*H + o0];
                float4 wb = *(const float4*)&s[OFF_S1V + (2*j+1)*H + o0];
                float cj = tc[j], sj = tsn[j];
                vecs[(j+1)*H + o0 + 0] = s1[0]*(wb.x*cj - wa.x*sj);
                vecs[(j+1)*H + o0 + 1] = s1[1]*(wb.y*cj - wa.y*sj);
                vecs[(j+1)*H + o0 + 2] = s1[2]*(wb.z*cj - wa.z*sj);
                vecs[(j+1)*H + o0 + 3] = s1[3]*(wb.w*cj - wa.w*sj);
            }
        }
        __syncwarp();

        // ---- layer 2 fused over 7 vectors (k-pair packed) + gravity dot with W3V
        {
            ull acc[7][4];
            #pragma unroll
            for (int t=0;t<4;t++) acc[0][t] = pk2(s[OFF_B2V + lane + 32*t], 0.0f);
            #pragma unroll
            for (int v=1;v<7;v++){
                #pragma unroll
                for (int t=0;t<4;t++) acc[v][t] = 0ull;
            }
            for (int k=0;k<H;k+=4){
                ulonglong2 hv[7];
                #pragma unroll
                for (int v=0;v<7;v++) hv[v] = *(const ulonglong2*)&vecs[v*H + k];
                #pragma unroll
                for (int p=0;p<2;p++){
                    const float* wrow = &s[OFF_S2V + ((k>>1)+p)*256];
                    ull wt[4];
                    #pragma unroll
                    for (int t=0;t<4;t++) wt[t] = *(const ull*)&wrow[(lane+32*t)*2];
                    #pragma unroll
                    for (int v=0;v<7;v++){
                        ull hp = p ? hv[v].y : hv[v].x;
                        #pragma unroll
                        for (int t=0;t<4;t++) acc[v][t] = ffma2(wt[t], hp, acc[v][t]);
                    }
                }
            }
            float pj[6];
            #pragma unroll
            for (int j=0;j<6;j++) pj[j]=0.f;
            #pragma unroll
            for (int t=0;t<4;t++){
                float wv = s[OFF_W3V + lane+32*t] * sig_f(hsum2(acc[0][t]));
                #pragma unroll
                for (int j=0;j<6;j++) pj[j] += wv*hsum2(acc[j+1][t]);
            }
            #pragma unroll
            for (int j=0;j<6;j++){
                float g = wsum(pj[j]);
                if (lane == 0) gsm[j] = g;
            }
        }
        __syncwarp();

        // ---- dM_j lower-tri entries
        for (int t = lane; t < 126; t += 32){
            int j = t/21, u = t%21;
            int a = c_TI[u], b = c_TJ[u];
            int ta = a*(a+1)/2, tb = b*(b+1)/2;
            const float* Lr = ydy;
            const float* Dr = ydy + (j+1)*21;
            float sacc = 0.f;
            for (int m = 0; m <= b; m++)
                sacc += Dr[ta+m]*Lr[tb+m] + Lr[ta+m]*Dr[tb+m];
            dmj[t] = sacc;
        }
        __syncwarp();

        // ---- P = sum_j qdot_j dM_j
        if (lane < 21){
            float p = 0.f;
            #pragma unroll
            for (int j=0;j<6;j++) p += qdr[j]*dmj[j*21+lane];
            psm[lane] = p;
        }
        __syncwarp();

        // ---- c_i, constraints, rhs
        if (lane < 6){
            int i = lane;
            float c1 = 0.f;
            #pragma unroll
            for (int b=0;b<6;b++){
                int idx = (i >= b) ? (i*(i+1)/2 + b) : (b*(b+1)/2 + i);
                c1 += psm[idx]*qdr[b];
            }
            float qf = 0.f;   // 0.5 * qd^T dM_i qd
            for (int u2=0; u2<21; u2++){
                int a = c_TI[u2], b = c_TJ[u2];
                float w = (a==b) ? 0.5f : 1.0f;
                qf += w*dmj[i*21+u2]*qdsh[a]*qdsh[b];
            }
            float ci = c1 - qf;
            float qi = qsh[i];
            float lo = c_LOWER[i] + 0.1f;
            float up = c_UPPER[i] - 0.1f;
            float fi;
            if (mask & (1u << i))
                fi = (qi <= lo) ? c_EFFORT[i] : ((qi >= up) ? -c_EFFORT[i] : 0.0f);
            else
                fi = -5.0f*(__fdividef(1.0f, qi-lo) - __fdividef(1.0f, up-qi));
            float tau = action[e*6+i]*c_EFFORT[i];
            rhssm[i] = tau - ci - gsm[i] - fi;
        }
        __syncwarp();

        // ---- solve (L L^T) x = rhs via fwd/back substitution
        if (lane == 0){
            float Lm[6][6];
            #pragma unroll
            for (int i=0;i<6;i++){
                #pragma unroll
                for (int jj=0;jj<6;jj++)
                    Lm[i][jj] = (jj<=i) ? ydy[i*(i+1)/2+jj] : 0.f;
            }
            float rinv[6];
            #pragma unroll
            for (int i=0;i<6;i++) rinv[i] = __fdividef(1.0f, Lm[i][i]);
            float wv[6], x[6];
            #pragma unroll
            for (int i=0;i<6;i++){
                float sr = rhssm[i];
                #pragma unroll
                for (int jj=0;jj<6;jj++) if (jj < i) sr -= Lm[i][jj]*wv[jj];
                wv[i] = sr * rinv[i];
            }
            #pragma unroll
            for (int i=5;i>=0;i--){
                float sr = wv[i];
                #pragma unroll
                for (int jj=0;jj<6;jj++) if (jj > i) sr -= Lm[jj][i]*x[jj];
                x[i] = sr * rinv[i];
            }
            #pragma unroll
            for (int i=0;i<6;i++) kout[e*6+i] = x[i];
        }
        __syncwarp();
    }
}

// ---------------- final RK4 combine ----------------
__global__ void stageFK(const float* __restrict__ obs, float* __restrict__ out){
    int e = blockIdx.x*blockDim.x + threadIdx.x;
    if (e >= BATCH) return;
    #pragma unroll
    for (int i=0;i<6;i++){
        float q  = obs[e*12 + i];
        float qd = obs[e*12 + 6 + i];
        float k1 = g_kqd[0][e*6+i];
        float k2 = g_kqd[1][e*6+i];
        float k3 = g_kqd[2][e*6+i];
        float k4 = g_kqd[3][e*6+i];
        float k1q = qd;
        float k2q = qd + 0.5f*DTc*k1;
        float k3q = qd + 0.5f*DTc*k2;
        float k4q = qd + DTc*k3;
        float qn  = q  + (DTc/6.0f)*(k1q + 2.f*k2q + 2.f*k3q + k4q);
        float qdn = qd + (DTc/6.0f)*(k1  + 2.f*k2  + 2.f*k3  + k4 );
        qn = fminf(fmaxf(qn, c_LOWER[i]), c_UPPER[i]);
        out[e*12 + i]     = qn;
        out[e*12 + 6 + i] = qdn;
    }
}

extern "C" void kernel_launch(void* const* d_in, const int* in_sizes, int n_in,
                              void* d_out, int out_size)
{
    const float* obs    = (const float*)d_in[0];
    const float* action = (const float*)d_in[1];
    const float* W1L = (const float*)d_in[2];  const float* b1L = (const float*)d_in[3];
    const float* W2L = (const float*)d_in[4];  const float* b2L = (const float*)d_in[5];
    const float* W3L = (const float*)d_in[6];  const float* b3L = (const float*)d_in[7];
    const float* W1V = (const float*)d_in[8];  const float* b1V = (const float*)d_in[9];
    const float* W2V = (const float*)d_in[10]; const float* b2V = (const float*)d_in[11];
    const float* W3V = (const float*)d_in[12];
    float* out = (float*)d_out;

    cudaFuncSetAttribute(stageBK, cudaFuncAttributeMaxDynamicSharedMemorySize, SMEM_BYTES);

    zeroMaskK<<<1, 32>>>();
    for (int st = 0; st < 4; st++){
        stageAK<<<BATCH/256, 256>>>(obs, st);
        stageBK<<<NBLK, TPB, SMEM_BYTES>>>(W1L,b1L,W2L,b2L,W3L,b3L,
                                           W1V,b1V,W2V,b2V,W3V, action, st);
    }
    stageFK<<<BATCH/256, 256>>>(obs, out);
}

// round 6
// speedup vs baseline: 1.6012x; 1.6012x over previous
#include <cuda_runtime.h>
#include <math.h>

#define BATCH 16384
#define B6 (BATCH*6)
#define H 128
#define DTc 0.01f
#define WARPS 13
#define TPB (WARPS*32)
#define NBLK 152

// ---- shared-memory weight layout (float offsets) ----
// S2L/S2V: k-pair interleaved [k/2][128*2]: (k,m) -> (k>>1)*256 + m*2 + (k&1)
// S3P:     k-pair interleaved [k/2][48]:    (k,o) -> (k>>1)*48 + o*2 + (k&1)
#define OFF_S1L 0        // [12][128]  W1L^T
#define OFF_S2L 1536     // 16384
#define OFF_S3P 17920    // 3072
#define OFF_B1L 20992
#define OFF_B2L 21120
#define OFF_B3L 21248    // 24 slots (21 used)
#define OFF_S1V 21272    // [12][128]  W1V^T
#define OFF_S2V 22808    // 16384
#define OFF_W3V 39192
#define OFF_B1V 39320
#define OFF_B2V 39448
#define WTOT    39576
#define SCR     1280     // per-warp scratch floats
#define SMEM_FLOATS (WTOT + WARPS*SCR)
#define SMEM_BYTES  (SMEM_FLOATS*4)

typedef unsigned long long ull;

__device__ float g_qs[B6];
__device__ float g_qds[B6];
__device__ float g_kqd[4][B6];
__device__ unsigned g_mask[4];

__constant__ float c_LOWER[6]  = {-6.28f,-6.28f,-3.14f,-6.28f,-6.28f,-6.28f};
__constant__ float c_UPPER[6]  = { 6.28f, 6.28f, 3.14f, 6.28f, 6.28f, 6.28f};
__constant__ float c_EFFORT[6] = {150.f,150.f,150.f,28.f,28.f,28.f};
__constant__ int   c_TI[21] = {0,1,1,2,2,2,3,3,3,3,4,4,4,4,4,5,5,5,5,5,5};
__constant__ int   c_TJ[21] = {0,0,1,0,1,2,0,1,2,3,0,1,2,3,4,0,1,2,3,4,5};

// ---- packed fp32x2 helpers ----
__device__ __forceinline__ ull pk2(float a, float b){
    ull r; asm("mov.b64 %0, {%1, %2};" : "=l"(r) : "f"(a), "f"(b)); return r;
}
__device__ __forceinline__ void upk2(ull v, float& a, float& b){
    asm("mov.b64 {%0, %1}, %2;" : "=f"(a), "=f"(b) : "l"(v));
}
__device__ __forceinline__ ull ffma2(ull a, ull b, ull c){
    ull d; asm("fma.rn.f32x2 %0, %1, %2, %3;" : "=l"(d) : "l"(a), "l"(b), "l"(c)); return d;
}
__device__ __forceinline__ float hsum2(ull v){
    float a, b; upk2(v, a, b); return a + b;
}

// fast softplus + sigmoid sharing one exp
__device__ __forceinline__ void spsig(float x, float& sp, float& sg){
    float e = __expf(-fabsf(x));
    float r = __fdividef(1.0f, 1.0f + e);
    sp = fmaxf(x, 0.0f) + __logf(1.0f + e);
    sg = (x >= 0.0f) ? r : (1.0f - r);
}
__device__ __forceinline__ float sig_f(float x){
    float e = __expf(-fabsf(x));
    float r = __fdividef(1.0f, 1.0f + e);
    return (x >= 0.0f) ? r : (1.0f - r);
}
__device__ __forceinline__ float wsum(float v){
    #pragma unroll
    for (int o = 16; o; o >>= 1) v += __shfl_xor_sync(0xffffffffu, v, o);
    return v;
}

// ---------------- mask zeroing ----------------
__global__ void zeroMaskK(){
    if (threadIdx.x < 4) g_mask[threadIdx.x] = 0u;
}

// ---------------- stage state + violation mask ----------------
__global__ void stageAK(const float* __restrict__ obs, int stage){
    int e = blockIdx.x*blockDim.x + threadIdx.x;
    unsigned bits = 0u;
    if (e < BATCH){
        #pragma unroll
        for (int i = 0; i < 6; i++){
            float q  = obs[e*12 + i];
            float qd = obs[e*12 + 6 + i];
            float qs, qds;
            if (stage == 0){
                qs = q; qds = qd;
            } else if (stage == 1){
                float k1 = g_kqd[0][e*6+i];
                qs  = q + 0.5f*DTc*qd;
                qds = qd + 0.5f*DTc*k1;
            } else if (stage == 2){
                float k1 = g_kqd[0][e*6+i];
                float k2 = g_kqd[1][e*6+i];
                float k2q = qd + 0.5f*DTc*k1;
                qs  = q + 0.5f*DTc*k2q;
                qds = qd + 0.5f*DTc*k2;
            } else {
                float k2 = g_kqd[1][e*6+i];
                float k3 = g_kqd[2][e*6+i];
                float k3q = qd + 0.5f*DTc*k2;
                qs  = q + DTc*k3q;
                qds = qd + DTc*k3;
            }
            g_qs[e*6+i]  = qs;
            g_qds[e*6+i] = qds;
            float lo = c_LOWER[i] + 0.1f;
            float up = c_UPPER[i] - 0.1f;
            if (qs <= lo || qs >= up) bits |= (1u << i);
        }
    }
    if (bits) atomicOr(&g_mask[stage], bits);
}

// ---------------- heavy accel kernel ----------------
__global__ void __launch_bounds__(TPB, 1) stageBK(
    const float* __restrict__ W1L, const float* __restrict__ b1L,
    const float* __restrict__ W2L, const float* __restrict__ b2L,
    const float* __restrict__ W3L, const float* __restrict__ b3L,
    const float* __restrict__ W1V, const float* __restrict__ b1V,
    const float* __restrict__ W2V, const float* __restrict__ b2V,
    const float* __restrict__ W3V, const float* __restrict__ action,
    int stage)
{
    extern __shared__ float s[];
    const int tid = threadIdx.x;

    // stage weights into shared
    for (int i = tid; i < 12*H; i += TPB) s[OFF_S1L + (i%12)*H + i/12] = W1L[i];
    for (int i = tid; i < H*H;  i += TPB){
        int m = i / H, k = i % H;
        s[OFF_S2L + (k>>1)*256 + m*2 + (k&1)] = W2L[i];
    }
    for (int i = tid; i < 21*H; i += TPB){
        int o = i / H, k = i % H;
        s[OFF_S3P + (k>>1)*48 + o*2 + (k&1)] = W3L[i];
    }
    for (int i = tid; i < 12*H; i += TPB) s[OFF_S1V + (i%12)*H + i/12] = W1V[i];
    for (int i = tid; i < H*H;  i += TPB){
        int m = i / H, k = i % H;
        s[OFF_S2V + (k>>1)*256 + m*2 + (k&1)] = W2V[i];
    }
    for (int i = tid; i < H; i += TPB){
        s[OFF_B1L+i]=b1L[i]; s[OFF_B2L+i]=b2L[i];
        s[OFF_B1V+i]=b1V[i]; s[OFF_B2V+i]=b2V[i];
        s[OFF_W3V+i]=W3V[i];
    }
    for (int i = tid; i < 21; i += TPB) s[OFF_B3L+i]=b3L[i];
    __syncthreads();

    const unsigned mask = g_mask[stage];
    const int wid = tid >> 5, lane = tid & 31;
    float* scr   = s + WTOT + wid*SCR;
    float* vecs  = scr;
    float* ydy   = scr + 896;
    float* dmj   = scr + 1048;
    float* psm   = scr + 1176;
    float* gsm   = scr + 1200;
    float* rhssm = scr + 1208;
    float* qsh   = scr + 1216;
    float* qdsh  = scr + 1224;
    float* tcsm  = scr + 1232;
    float* tssm  = scr + 1240;
    const int o0 = lane*4;
    float* kout = g_kqd[stage];

    for (int e = blockIdx.x*WARPS + wid; e < BATCH; e += gridDim.x*WARPS){
        if (lane < 6){
            float qv  = g_qs[e*6+lane];
            float qdv = g_qds[e*6+lane];
            qsh[lane]  = qv;
            qdsh[lane] = qdv;
            float sn, cs;
            __sincosf(qv, &sn, &cs);
            tcsm[lane] = cs;
            tssm[lane] = sn;
        }
        __syncwarp();

        // ==================== L network ====================
        // ---- layer 1: h1 + 6 tangents (block m-ownership o0..o0+3)
        {
            float zz[4];
            #pragma unroll
            for (int m=0;m<4;m++) zz[m] = s[OFF_B1L+o0+m];
            #pragma unroll
            for (int k=0;k<12;k++){
                float tk = (k&1) ? tssm[k>>1] : tcsm[k>>1];
                float4 w = *(const float4*)&s[OFF_S1L + k*H + o0];
                zz[0]+=w.x*tk; zz[1]+=w.y*tk; zz[2]+=w.z*tk; zz[3]+=w.w*tk;
            }
            float s1[4];
            #pragma unroll
            for (int m=0;m<4;m++){
                float spv, sgv; spsig(zz[m], spv, sgv);
                vecs[o0+m] = spv; s1[m] = sgv;
            }
            #pragma unroll
            for (int j=0;j<6;j++){
                float4 wa = *(const float4*)&s[OFF_S1L + (2*j  )*H + o0];
                float4 wb = *(const float4*)&s[OFF_S1L + (2*j+1)*H + o0];
                float cj = tcsm[j], sj = tssm[j];
                vecs[(j+1)*H + o0 + 0] = s1[0]*(wb.x*cj - wa.x*sj);
                vecs[(j+1)*H + o0 + 1] = s1[1]*(wb.y*cj - wa.y*sj);
                vecs[(j+1)*H + o0 + 2] = s1[2]*(wb.z*cj - wa.z*sj);
                vecs[(j+1)*H + o0 + 3] = s1[3]*(wb.w*cj - wa.w*sj);
            }
        }
        __syncwarp();

        // ---- layer 2: k-pair packed, m-strided ownership, two v-passes
        {
            float s2v[4];
            // pass A: v = 0..3
            {
                ull acc[4][4];
                #pragma unroll
                for (int t=0;t<4;t++) acc[0][t] = pk2(s[OFF_B2L + lane + 32*t], 0.0f);
                #pragma unroll
                for (int v=1;v<4;v++){
                    #pragma unroll
                    for (int t=0;t<4;t++) acc[v][t] = 0ull;
                }
                for (int k=0;k<H;k+=4){
                    ulonglong2 hv[4];
                    #pragma unroll
                    for (int v=0;v<4;v++) hv[v] = *(const ulonglong2*)&vecs[v*H + k];
                    #pragma unroll
                    for (int p=0;p<2;p++){
                        const float* wrow = &s[OFF_S2L + ((k>>1)+p)*256];
                        ull wt[4];
                        #pragma unroll
                        for (int t=0;t<4;t++) wt[t] = *(const ull*)&wrow[(lane+32*t)*2];
                        #pragma unroll
                        for (int v=0;v<4;v++){
                            ull hp = p ? hv[v].y : hv[v].x;
                            #pragma unroll
                            for (int t=0;t<4;t++) acc[v][t] = ffma2(wt[t], hp, acc[v][t]);
                        }
                    }
                }
                __syncwarp();   // all lanes done reading vecs[0..3] before overwrite
                #pragma unroll
                for (int t=0;t<4;t++){
                    float spv, sgv; spsig(hsum2(acc[0][t]), spv, sgv);
                    vecs[lane+32*t] = spv; s2v[t] = sgv;
                }
                #pragma unroll
                for (int v=1;v<4;v++){
                    #pragma unroll
                    for (int t=0;t<4;t++) vecs[v*H + lane+32*t] = s2v[t]*hsum2(acc[v][t]);
                }
            }
            // pass B: v = 4..6 (reads only vecs[4H..7H), untouched by pass A writes)
            {
                ull acc[3][4];
                #pragma unroll
                for (int v=0;v<3;v++){
                    #pragma unroll
                    for (int t=0;t<4;t++) acc[v][t] = 0ull;
                }
                for (int k=0;k<H;k+=4){
                    ulonglong2 hv[3];
                    #pragma unroll
                    for (int v=0;v<3;v++) hv[v] = *(const ulonglong2*)&vecs[(v+4)*H + k];
                    #pragma unroll
                    for (int p=0;p<2;p++){
                        const float* wrow = &s[OFF_S2L + ((k>>1)+p)*256];
                        ull wt[4];
                        #pragma unroll
                        for (int t=0;t<4;t++) wt[t] = *(const ull*)&wrow[(lane+32*t)*2];
                        #pragma unroll
                        for (int v=0;v<3;v++){
                            ull hp = p ? hv[v].y : hv[v].x;
                            #pragma unroll
                            for (int t=0;t<4;t++) acc[v][t] = ffma2(wt[t], hp, acc[v][t]);
                        }
                    }
                }
                __syncwarp();
                #pragma unroll
                for (int v=0;v<3;v++){
                    #pragma unroll
                    for (int t=0;t<4;t++) vecs[(v+4)*H + lane+32*t] = s2v[t]*hsum2(acc[v][t]);
                }
            }
        }
        __syncwarp();

        // ---- layer 3 (21 outputs), k-pair packed
        if (lane < 21){
            ull facc[7];
            facc[0] = pk2(s[OFF_B3L+lane], 0.0f);
            #pragma unroll
            for (int v=1;v<7;v++) facc[v] = 0ull;
            for (int k=0;k<H;k+=4){
                ulonglong2 hv[7];
                #pragma unroll
                for (int v=0;v<7;v++) hv[v] = *(const ulonglong2*)&vecs[v*H + k];
                #pragma unroll
                for (int p=0;p<2;p++){
                    ull wp = *(const ull*)&s[OFF_S3P + ((k>>1)+p)*48 + lane*2];
                    #pragma unroll
                    for (int v=0;v<7;v++)
                        facc[v] = ffma2(wp, p ? hv[v].y : hv[v].x, facc[v]);
                }
            }
            float spv, s3; spsig(hsum2(facc[0]), spv, s3);
            ydy[lane] = spv;
            #pragma unroll
            for (int v=1;v<7;v++) ydy[v*21+lane] = s3*hsum2(facc[v]);
        }
        __syncwarp();

        // ==================== V network (forward-mode gradient) ====================
        // ---- layer 1: value + 6 tangents (overwrite vecs)
        {
            float zz[4];
            #pragma unroll
            for (int m=0;m<4;m++) zz[m] = s[OFF_B1V+o0+m];
            #pragma unroll
            for (int k=0;k<12;k++){
                float tk = (k&1) ? tssm[k>>1] : tcsm[k>>1];
                float4 w = *(const float4*)&s[OFF_S1V + k*H + o0];
                zz[0]+=w.x*tk; zz[1]+=w.y*tk; zz[2]+=w.z*tk; zz[3]+=w.w*tk;
            }
            float s1[4];
            #pragma unroll
            for (int m=0;m<4;m++){
                float spv, sgv; spsig(zz[m], spv, sgv);
                vecs[o0+m] = spv; s1[m] = sgv;
            }
            #pragma unroll
            for (int j=0;j<6;j++){
                float4 wa = *(const float4*)&s[OFF_S1V + (2*j  )*H + o0];
                float4 wb = *(const float4*)&s[OFF_S1V + (2*j+1)*H + o0];
                float cj = tcsm[j], sj = tssm[j];
                vecs[(j+1)*H + o0 + 0] = s1[0]*(wb.x*cj - wa.x*sj);
                vecs[(j+1)*H + o0 + 1] = s1[1]*(wb.y*cj - wa.y*sj);
                vecs[(j+1)*H + o0 + 2] = s1[2]*(wb.z*cj - wa.z*sj);
                vecs[(j+1)*H + o0 + 3] = s1[3]*(wb.w*cj - wa.w*sj);
            }
        }
        __syncwarp();

        // ---- layer 2: two v-passes, gravity dot with W3V (register-only outputs)
        {
            float pj[6];
            float wv4[4];
            // pass A: v = 0..3
            {
                ull acc[4][4];
                #pragma unroll
                for (int t=0;t<4;t++) acc[0][t] = pk2(s[OFF_B2V + lane + 32*t], 0.0f);
                #pragma unroll
                for (int v=1;v<4;v++){
                    #pragma unroll
                    for (int t=0;t<4;t++) acc[v][t] = 0ull;
                }
                for (int k=0;k<H;k+=4){
                    ulonglong2 hv[4];
                    #pragma unroll
                    for (int v=0;v<4;v++) hv[v] = *(const ulonglong2*)&vecs[v*H + k];
                    #pragma unroll
                    for (int p=0;p<2;p++){
                        const float* wrow = &s[OFF_S2V + ((k>>1)+p)*256];
                        ull wt[4];
                        #pragma unroll
                        for (int t=0;t<4;t++) wt[t] = *(const ull*)&wrow[(lane+32*t)*2];
                        #pragma unroll
                        for (int v=0;v<4;v++){
                            ull hp = p ? hv[v].y : hv[v].x;
                            #pragma unroll
                            for (int t=0;t<4;t++) acc[v][t] = ffma2(wt[t], hp, acc[v][t]);
                        }
                    }
                }
                #pragma unroll
                for (int t=0;t<4;t++)
                    wv4[t] = s[OFF_W3V + lane+32*t] * sig_f(hsum2(acc[0][t]));
                #pragma unroll
                for (int j=0;j<3;j++){
                    float p = 0.f;
                    #pragma unroll
                    for (int t=0;t<4;t++) p += wv4[t]*hsum2(acc[j+1][t]);
                    pj[j] = p;
                }
            }
            // pass B: v = 4..6
            {
                ull acc[3][4];
                #pragma unroll
                for (int v=0;v<3;v++){
                    #pragma unroll
                    for (int t=0;t<4;t++) acc[v][t] = 0ull;
                }
                for (int k=0;k<H;k+=4){
                    ulonglong2 hv[3];
                    #pragma unroll
                    for (int v=0;v<3;v++) hv[v] = *(const ulonglong2*)&vecs[(v+4)*H + k];
                    #pragma unroll
                    for (int p=0;p<2;p++){
                        const float* wrow = &s[OFF_S2V + ((k>>1)+p)*256];
                        ull wt[4];
                        #pragma unroll
                        for (int t=0;t<4;t++) wt[t] = *(const ull*)&wrow[(lane+32*t)*2];
                        #pragma unroll
                        for (int v=0;v<3;v++){
                            ull hp = p ? hv[v].y : hv[v].x;
                            #pragma unroll
                            for (int t=0;t<4;t++) acc[v][t] = ffma2(wt[t], hp, acc[v][t]);
                        }
                    }
                }
                #pragma unroll
                for (int j=0;j<3;j++){
                    float p = 0.f;
                    #pragma unroll
                    for (int t=0;t<4;t++) p += wv4[t]*hsum2(acc[j][t]);
                    pj[3+j] = p;
                }
            }
            #pragma unroll
            for (int j=0;j<6;j++){
                float g = wsum(pj[j]);
                if (lane == 0) gsm[j] = g;
            }
        }
        __syncwarp();

        // ---- dM_j lower-tri entries
        for (int t = lane; t < 126; t += 32){
            int j = t/21, u = t%21;
            int a = c_TI[u], b = c_TJ[u];
            int ta = a*(a+1)/2, tb = b*(b+1)/2;
            const float* Lr = ydy;
            const float* Dr = ydy + (j+1)*21;
            float sacc = 0.f;
            for (int m = 0; m <= b; m++)
                sacc += Dr[ta+m]*Lr[tb+m] + Lr[ta+m]*Dr[tb+m];
            dmj[t] = sacc;
        }
        __syncwarp();

        // ---- P = sum_j qdot_j dM_j
        if (lane < 21){
            float p = 0.f;
            #pragma unroll
            for (int j=0;j<6;j++) p += qdsh[j]*dmj[j*21+lane];
            psm[lane] = p;
        }
        __syncwarp();

        // ---- c_i, constraints, rhs
        if (lane < 6){
            int i = lane;
            float c1 = 0.f;
            #pragma unroll
            for (int b=0;b<6;b++){
                int idx = (i >= b) ? (i*(i+1)/2 + b) : (b*(b+1)/2 + i);
                c1 += psm[idx]*qdsh[b];
            }
            float qf = 0.f;   // 0.5 * qd^T dM_i qd
            for (int u2=0; u2<21; u2++){
                int a = c_TI[u2], b = c_TJ[u2];
                float w = (a==b) ? 0.5f : 1.0f;
                qf += w*dmj[i*21+u2]*qdsh[a]*qdsh[b];
            }
            float ci = c1 - qf;
            float qi = qsh[i];
            float lo = c_LOWER[i] + 0.1f;
            float up = c_UPPER[i] - 0.1f;
            float fi;
            if (mask & (1u << i))
                fi = (qi <= lo) ? c_EFFORT[i] : ((qi >= up) ? -c_EFFORT[i] : 0.0f);
            else
                fi = -5.0f*(__fdividef(1.0f, qi-lo) - __fdividef(1.0f, up-qi));
            float tau = action[e*6+i]*c_EFFORT[i];
            rhssm[i] = tau - ci - gsm[i] - fi;
        }
        __syncwarp();

        // ---- solve (L L^T) x = rhs via fwd/back substitution
        if (lane == 0){
            float Lm[6][6];
            #pragma unroll
            for (int i=0;i<6;i++){
                #pragma unroll
                for (int jj=0;jj<6;jj++)
                    Lm[i][jj] = (jj<=i) ? ydy[i*(i+1)/2+jj] : 0.f;
            }
            float rinv[6];
            #pragma unroll
            for (int i=0;i<6;i++) rinv[i] = __fdividef(1.0f, Lm[i][i]);
            float wv[6], x[6];
            #pragma unroll
            for (int i=0;i<6;i++){
                float sr = rhssm[i];
                #pragma unroll
                for (int jj=0;jj<6;jj++) if (jj < i) sr -= Lm[i][jj]*wv[jj];
                wv[i] = sr * rinv[i];
            }
            #pragma unroll
            for (int i=5;i>=0;i--){
                float sr = wv[i];
                #pragma unroll
                for (int jj=0;jj<6;jj++) if (jj > i) sr -= Lm[jj][i]*x[jj];
                x[i] = sr * rinv[i];
            }
            #pragma unroll
            for (int i=0;i<6;i++) kout[e*6+i] = x[i];
        }
        __syncwarp();
    }
}

// ---------------- final RK4 combine ----------------
__global__ void stageFK(const float* __restrict__ obs, float* __restrict__ out){
    int e = blockIdx.x*blockDim.x + threadIdx.x;
    if (e >= BATCH) return;
    #pragma unroll
    for (int i=0;i<6;i++){
        float q  = obs[e*12 + i];
        float qd = obs[e*12 + 6 + i];
        float k1 = g_kqd[0][e*6+i];
        float k2 = g_kqd[1][e*6+i];
        float k3 = g_kqd[2][e*6+i];
        float k4 = g_kqd[3][e*6+i];
        float k1q = qd;
        float k2q = qd + 0.5f*DTc*k1;
        float k3q = qd + 0.5f*DTc*k2;
        float k4q = qd + DTc*k3;
        float qn  = q  + (DTc/6.0f)*(k1q + 2.f*k2q + 2.f*k3q + k4q);
        float qdn = qd + (DTc/6.0f)*(k1  + 2.f*k2  + 2.f*k3  + k4 );
        qn = fminf(fmaxf(qn, c_LOWER[i]), c_UPPER[i]);
        out[e*12 + i]     = qn;
        out[e*12 + 6 + i] = qdn;
    }
}

extern "C" void kernel_launch(void* const* d_in, const int* in_sizes, int n_in,
                              void* d_out, int out_size)
{
    const float* obs    = (const float*)d_in[0];
    const float* action = (const float*)d_in[1];
    const float* W1L = (const float*)d_in[2];  const float* b1L = (const float*)d_in[3];
    const float* W2L = (const float*)d_in[4];  const float* b2L = (const float*)d_in[5];
    const float* W3L = (const float*)d_in[6];  const float* b3L = (const float*)d_in[7];
    const float* W1V = (const float*)d_in[8];  const float* b1V = (const float*)d_in[9];
    const float* W2V = (const float*)d_in[10]; const float* b2V = (const float*)d_in[11];
    const float* W3V = (const float*)d_in[12];
    float* out = (float*)d_out;

    cudaFuncSetAttribute(stageBK, cudaFuncAttributeMaxDynamicSharedMemorySize, SMEM_BYTES);

    zeroMaskK<<<1, 32>>>();
    for (int st = 0; st < 4; st++){
        stageAK<<<BATCH/256, 256>>>(obs, st);
        stageBK<<<NBLK, TPB, SMEM_BYTES>>>(W1L,b1L,W2L,b2L,W3L,b3L,
                                           W1V,b1V,W2V,b2V,W3V, action, st);
    }
    stageFK<<<BATCH/256, 256>>>(obs, out);
}

// round 8
// speedup vs baseline: 2.0136x; 1.2576x over previous
#include <cuda_runtime.h>
#include <math.h>

#define BATCH 16384
#define B6 (BATCH*6)
#define H 128
#define DTc 0.01f
#define WARPS 14
#define TPB (WARPS*32)
#define NBLK 152

// ---- shared-memory weight layout (float offsets) ----
#define OFF_S1L 0        // [12][128]  W1L^T
#define OFF_S2L 1536     // [128][128] W2L^T (in-major)
#define OFF_S3L 17920    // [128][21]  W3L^T
#define OFF_B1L 20608
#define OFF_B2L 20736
#define OFF_B3L 20864    // 24 slots (21 used)
#define OFF_S1V 20888    // [12][128]  W1V^T
#define OFF_S2V 22424    // [128][128] W2V^T (in-major)
#define OFF_W3V 38808    // [128]
#define OFF_B1V 38936
#define OFF_B2V 39064
#define WTOT    39192
#define SCR     1280     // per-warp scratch floats
#define SMEM_FLOATS (WTOT + WARPS*SCR)
#define SMEM_BYTES  (SMEM_FLOATS*4)

typedef unsigned long long ull;

__device__ float g_qs[B6];
__device__ float g_qds[B6];
__device__ float g_kqd[4][B6];
__device__ unsigned g_mask[4];

__constant__ float c_LOWER[6]  = {-6.28f,-6.28f,-3.14f,-6.28f,-6.28f,-6.28f};
__constant__ float c_UPPER[6]  = { 6.28f, 6.28f, 3.14f, 6.28f, 6.28f, 6.28f};
__constant__ float c_EFFORT[6] = {150.f,150.f,150.f,28.f,28.f,28.f};
__constant__ int   c_TI[21] = {0,1,1,2,2,2,3,3,3,3,4,4,4,4,4,5,5,5,5,5,5};
__constant__ int   c_TJ[21] = {0,0,1,0,1,2,0,1,2,3,0,1,2,3,4,0,1,2,3,4,5};

// ---- packed fp32x2 helpers (Blackwell FFMA2 path) ----
__device__ __forceinline__ ull pk2(float a, float b){
    ull r; asm("mov.b64 %0, {%1, %2};" : "=l"(r) : "f"(a), "f"(b)); return r;
}
__device__ __forceinline__ void upk2(ull v, float& a, float& b){
    asm("mov.b64 {%0, %1}, %2;" : "=f"(a), "=f"(b) : "l"(v));
}
__device__ __forceinline__ ull ffma2(ull a, ull b, ull c){
    ull d; asm("fma.rn.f32x2 %0, %1, %2, %3;" : "=l"(d) : "l"(a), "l"(b), "l"(c)); return d;
}

// fast softplus + sigmoid sharing one exp
__device__ __forceinline__ void spsig(float x, float& sp, float& sg){
    float e = __expf(-fabsf(x));
    float r = __fdividef(1.0f, 1.0f + e);
    sp = fmaxf(x, 0.0f) + __logf(1.0f + e);
    sg = (x >= 0.0f) ? r : (1.0f - r);
}
__device__ __forceinline__ float sig_f(float x){
    float e = __expf(-fabsf(x));
    float r = __fdividef(1.0f, 1.0f + e);
    return (x >= 0.0f) ? r : (1.0f - r);
}
__device__ __forceinline__ float wsum(float v){
    #pragma unroll
    for (int o = 16; o; o >>= 1) v += __shfl_xor_sync(0xffffffffu, v, o);
    return v;
}

// ---------------- mask zeroing ----------------
__global__ void zeroMaskK(){
    if (threadIdx.x < 4) g_mask[threadIdx.x] = 0u;
}

// ---------------- stage state + violation mask ----------------
__global__ void stageAK(const float* __restrict__ obs, int stage){
    int e = blockIdx.x*blockDim.x + threadIdx.x;
    unsigned bits = 0u;
    if (e < BATCH){
        #pragma unroll
        for (int i = 0; i < 6; i++){
            float q  = obs[e*12 + i];
            float qd = obs[e*12 + 6 + i];
            float qs, qds;
            if (stage == 0){
                qs = q; qds = qd;
            } else if (stage == 1){
                float k1 = g_kqd[0][e*6+i];
                qs  = q + 0.5f*DTc*qd;
                qds = qd + 0.5f*DTc*k1;
            } else if (stage == 2){
                float k1 = g_kqd[0][e*6+i];
                float k2 = g_kqd[1][e*6+i];
                float k2q = qd + 0.5f*DTc*k1;
                qs  = q + 0.5f*DTc*k2q;
                qds = qd + 0.5f*DTc*k2;
            } else {
                float k2 = g_kqd[1][e*6+i];
                float k3 = g_kqd[2][e*6+i];
                float k3q = qd + 0.5f*DTc*k2;
                qs  = q + DTc*k3q;
                qds = qd + DTc*k3;
            }
            g_qs[e*6+i]  = qs;
            g_qds[e*6+i] = qds;
            float lo = c_LOWER[i] + 0.1f;
            float up = c_UPPER[i] - 0.1f;
            if (qs <= lo || qs >= up) bits |= (1u << i);
        }
    }
    if (bits) atomicOr(&g_mask[stage], bits);
}

// ---------------- heavy accel kernel ----------------
__global__ void __launch_bounds__(TPB, 1) stageBK(
    const float* __restrict__ W1L, const float* __restrict__ b1L,
    const float* __restrict__ W2L, const float* __restrict__ b2L,
    const float* __restrict__ W3L, const float* __restrict__ b3L,
    const float* __restrict__ W1V, const float* __restrict__ b1V,
    const float* __restrict__ W2V, const float* __restrict__ b2V,
    const float* __restrict__ W3V, const float* __restrict__ action,
    int stage)
{
    extern __shared__ float s[];
    const int tid = threadIdx.x;

    // stage weights (transposed to in-major) into shared
    for (int i = tid; i < 12*H; i += TPB) s[OFF_S1L + (i%12)*H + i/12] = W1L[i];
    for (int i = tid; i < H*H;  i += TPB) s[OFF_S2L + (i%H)*H + i/H]  = W2L[i];
    for (int i = tid; i < 21*H; i += TPB) s[OFF_S3L + (i%H)*21 + i/H] = W3L[i];
    for (int i = tid; i < 12*H; i += TPB) s[OFF_S1V + (i%12)*H + i/12] = W1V[i];
    for (int i = tid; i < H*H;  i += TPB) s[OFF_S2V + (i%H)*H + i/H]  = W2V[i];
    for (int i = tid; i < H; i += TPB){
        s[OFF_B1L+i]=b1L[i]; s[OFF_B2L+i]=b2L[i];
        s[OFF_B1V+i]=b1V[i]; s[OFF_B2V+i]=b2V[i];
        s[OFF_W3V+i]=W3V[i];
    }
    for (int i = tid; i < 21; i += TPB) s[OFF_B3L+i]=b3L[i];
    __syncthreads();

    const unsigned mask = g_mask[stage];
    const int wid = tid >> 5, lane = tid & 31;
    float* scr   = s + WTOT + wid*SCR;
    float* vecs  = scr;
    float* ydy   = scr + 896;
    float* dmj   = scr + 1048;
    float* psm   = scr + 1176;
    float* gsm   = scr + 1200;
    float* rhssm = scr + 1208;
    float* qsh   = scr + 1216;
    float* qdsh  = scr + 1224;
    float* tcsm  = scr + 1232;
    float* tssm  = scr + 1240;
    const int o0 = lane*4;
    float* kout = g_kqd[stage];

    for (int e = blockIdx.x*WARPS + wid; e < BATCH; e += gridDim.x*WARPS){
        if (lane < 6){
            float qv  = g_qs[e*6+lane];
            float qdv = g_qds[e*6+lane];
            qsh[lane]  = qv;
            qdsh[lane] = qdv;
            float sn, cs;
            __sincosf(qv, &sn, &cs);
            tcsm[lane] = cs;
            tssm[lane] = sn;
        }
        __syncwarp();
        float tc[6], tsn[6], qdr[6];
        #pragma unroll
        for (int i = 0; i < 6; i++){ tc[i]=tcsm[i]; tsn[i]=tssm[i]; qdr[i]=qdsh[i]; }

        // ==================== L network ====================
        // ---- layer 1: h1 + 6 tangents
        {
            float zz[4];
            #pragma unroll
            for (int m=0;m<4;m++) zz[m] = s[OFF_B1L+o0+m];
            #pragma unroll
            for (int k=0;k<12;k++){
                float tk = (k&1) ? tsn[k>>1] : tc[k>>1];
                float4 w = *(const float4*)&s[OFF_S1L + k*H + o0];
                zz[0]+=w.x*tk; zz[1]+=w.y*tk; zz[2]+=w.z*tk; zz[3]+=w.w*tk;
            }
            float s1[4];
            #pragma unroll
            for (int m=0;m<4;m++){
                float spv, sgv; spsig(zz[m], spv, sgv);
                vecs[o0+m] = spv; s1[m] = sgv;
            }
            #pragma unroll
            for (int j=0;j<6;j++){
                float4 wa = *(const float4*)&s[OFF_S1L + (2*j  )*H + o0];
                float4 wb = *(const float4*)&s[OFF_S1L + (2*j+1)*H + o0];
                float cj = tc[j], sj = tsn[j];
                vecs[(j+1)*H + o0 + 0] = s1[0]*(wb.x*cj - wa.x*sj);
                vecs[(j+1)*H + o0 + 1] = s1[1]*(wb.y*cj - wa.y*sj);
                vecs[(j+1)*H + o0 + 2] = s1[2]*(wb.z*cj - wa.z*sj);
                vecs[(j+1)*H + o0 + 3] = s1[3]*(wb.w*cj - wa.w*sj);
            }
        }
        __syncwarp();

        // ---- layer 2, fused over 7 vectors (packed fp32x2 over m-pairs)
        {
            ull a01[7], a23[7];
            a01[0] = pk2(s[OFF_B2L+o0+0], s[OFF_B2L+o0+1]);
            a23[0] = pk2(s[OFF_B2L+o0+2], s[OFF_B2L+o0+3]);
            #pragma unroll
            for (int v=1;v<7;v++){ a01[v]=0ull; a23[v]=0ull; }
            for (int k=0;k<H;k+=4){
                float4 h4[7];
                #pragma unroll
                for (int v=0;v<7;v++) h4[v] = *(const float4*)&vecs[v*H + k];
                #pragma unroll
                for (int kk=0;kk<4;kk++){
                    float4 w = *(const float4*)&s[OFF_S2L + (k+kk)*H + o0];
                    ull w01 = pk2(w.x, w.y), w23 = pk2(w.z, w.w);
                    #pragma unroll
                    for (int v=0;v<7;v++){
                        float hs = (&h4[v].x)[kk];
                        ull h2 = pk2(hs, hs);
                        a01[v] = ffma2(w01, h2, a01[v]);
                        a23[v] = ffma2(w23, h2, a23[v]);
                    }
                }
            }
            __syncwarp();
            float av[7][4];
            #pragma unroll
            for (int v=0;v<7;v++){
                upk2(a01[v], av[v][0], av[v][1]);
                upk2(a23[v], av[v][2], av[v][3]);
            }
            float s2[4];
            #pragma unroll
            for (int m=0;m<4;m++){
                float spv, sgv; spsig(av[0][m], spv, sgv);
                vecs[o0+m] = spv; s2[m] = sgv;
            }
            #pragma unroll
            for (int v=1;v<7;v++){
                #pragma unroll
                for (int m=0;m<4;m++) vecs[v*H+o0+m] = s2[m]*av[v][m];
            }
        }
        __syncwarp();

        // ---- layer 3 (21 outputs) -> y, dy_j
        if (lane < 21){
            float f7[7];
            f7[0] = s[OFF_B3L+lane];
            #pragma unroll
            for (int v=1;v<7;v++) f7[v]=0.f;
            for (int k=0;k<H;k+=4){
                float w0 = s[OFF_S3L+(k+0)*21+lane];
                float w1 = s[OFF_S3L+(k+1)*21+lane];
                float w2 = s[OFF_S3L+(k+2)*21+lane];
                float w3 = s[OFF_S3L+(k+3)*21+lane];
                #pragma unroll
                for (int v=0;v<7;v++){
                    float4 h4 = *(const float4*)&vecs[v*H + k];
                    f7[v] += w0*h4.x + w1*h4.y + w2*h4.z + w3*h4.w;
                }
            }
            float spv, s3; spsig(f7[0], spv, s3);
            ydy[lane] = spv;
            #pragma unroll
            for (int v=1;v<7;v++) ydy[v*21+lane] = s3*f7[v];
        }
        __syncwarp();

        // ==================== V network (forward-mode gradient) ====================
        // ---- layer 1: value + 6 tangents (overwrite vecs)
        {
            float zz[4];
            #pragma unroll
            for (int m=0;m<4;m++) zz[m] = s[OFF_B1V+o0+m];
            #pragma unroll
            for (int k=0;k<12;k++){
                float tk = (k&1) ? tsn[k>>1] : tc[k>>1];
                float4 w = *(const float4*)&s[OFF_S1V + k*H + o0];
                zz[0]+=w.x*tk; zz[1]+=w.y*tk; zz[2]+=w.z*tk; zz[3]+=w.w*tk;
            }
            float s1[4];
            #pragma unroll
            for (int m=0;m<4;m++){
                float spv, sgv; spsig(zz[m], spv, sgv);
                vecs[o0+m] = spv; s1[m] = sgv;
            }
            #pragma unroll
            for (int j=0;j<6;j++){
                float4 wa = *(const float4*)&s[OFF_S1V + (2*j  )*H + o0];
                float4 wb = *(const float4*)&s[OFF_S1V + (2*j+1)*H + o0];
                float cj = tc[j], sj = tsn[j];
                vecs[(j+1)*H + o0 + 0] = s1[0]*(wb.x*cj - wa.x*sj);
                vecs[(j+1)*H + o0 + 1] = s1[1]*(wb.y*cj - wa.y*sj);
                vecs[(j+1)*H + o0 + 2] = s1[2]*(wb.z*cj - wa.z*sj);
                vecs[(j+1)*H + o0 + 3] = s1[3]*(wb.w*cj - wa.w*sj);
            }
        }
        __syncwarp();

        // ---- layer 2 fused over 7 vectors (packed) + gravity dot with W3V
        {
            ull a01[7], a23[7];
            a01[0] = pk2(s[OFF_B2V+o0+0], s[OFF_B2V+o0+1]);
            a23[0] = pk2(s[OFF_B2V+o0+2], s[OFF_B2V+o0+3]);
            #pragma unroll
            for (int v=1;v<7;v++){ a01[v]=0ull; a23[v]=0ull; }
            for (int k=0;k<H;k+=4){
                float4 h4[7];
                #pragma unroll
                for (int v=0;v<7;v++) h4[v] = *(const float4*)&vecs[v*H + k];
                #pragma unroll
                for (int kk=0;kk<4;kk++){
                    float4 w = *(const float4*)&s[OFF_S2V + (k+kk)*H + o0];
                    ull w01 = pk2(w.x, w.y), w23 = pk2(w.z, w.w);
                    #pragma unroll
                    for (int v=0;v<7;v++){
                        float hs = (&h4[v].x)[kk];
                        ull h2 = pk2(hs, hs);
                        a01[v] = ffma2(w01, h2, a01[v]);
                        a23[v] = ffma2(w23, h2, a23[v]);
                    }
                }
            }
            float av[7][4];
            #pragma unroll
            for (int v=0;v<7;v++){
                upk2(a01[v], av[v][0], av[v][1]);
                upk2(a23[v], av[v][2], av[v][3]);
            }
            float pj[6];
            #pragma unroll
            for (int j=0;j<6;j++) pj[j]=0.f;
            #pragma unroll
            for (int m=0;m<4;m++){
                float wv = s[OFF_W3V+o0+m] * sig_f(av[0][m]);
                #pragma unroll
                for (int j=0;j<6;j++) pj[j] += wv*av[j+1][m];
            }
            #pragma unroll
            for (int j=0;j<6;j++){
                float g = wsum(pj[j]);
                if (lane == 0) gsm[j] = g;
            }
        }
        __syncwarp();

        // ---- dM_j lower-tri entries
        for (int t = lane; t < 126; t += 32){
            int j = t/21, u = t%21;
            int a = c_TI[u], b = c_TJ[u];
            int ta = a*(a+1)/2, tb = b*(b+1)/2;
            const float* Lr = ydy;
            const float* Dr = ydy + (j+1)*21;
            float sacc = 0.f;
            for (int m = 0; m <= b; m++)
                sacc += Dr[ta+m]*Lr[tb+m] + Lr[ta+m]*Dr[tb+m];
            dmj[t] = sacc;
        }
        __syncwarp();

        // ---- P = sum_j qdot_j dM_j
        if (lane < 21){
            float p = 0.f;
            #pragma unroll
            for (int j=0;j<6;j++) p += qdr[j]*dmj[j*21+lane];
            psm[lane] = p;
        }
        __syncwarp();

        // ---- c_i, constraints, rhs
        if (lane < 6){
            int i = lane;
            float c1 = 0.f;
            #pragma unroll
            for (int b=0;b<6;b++){
                int idx = (i >= b) ? (i*(i+1)/2 + b) : (b*(b+1)/2 + i);
                c1 += psm[idx]*qdr[b];
            }
            float qf = 0.f;   // 0.5 * qd^T dM_i qd
            for (int u2=0; u2<21; u2++){
                int a = c_TI[u2], b = c_TJ[u2];
                float w = (a==b) ? 0.5f : 1.0f;
                qf += w*dmj[i*21+u2]*qdsh[a]*qdsh[b];
            }
            float ci = c1 - qf;
            float qi = qsh[i];
            float lo = c_LOWER[i] + 0.1f;
            float up = c_UPPER[i] - 0.1f;
            float fi;
            if (mask & (1u << i))
                fi = (qi <= lo) ? c_EFFORT[i] : ((qi >= up) ? -c_EFFORT[i] : 0.0f);
            else
                fi = -5.0f*(__fdividef(1.0f, qi-lo) - __fdividef(1.0f, up-qi));
            float tau = action[e*6+i]*c_EFFORT[i];
            rhssm[i] = tau - ci - gsm[i] - fi;
        }
        __syncwarp();

        // ---- solve (L L^T) x = rhs via fwd/back substitution
        if (lane == 0){
            float Lm[6][6];
            #pragma unroll
            for (int i=0;i<6;i++){
                #pragma unroll
                for (int jj=0;jj<6;jj++)
                    Lm[i][jj] = (jj<=i) ? ydy[i*(i+1)/2+jj] : 0.f;
            }
            float rinv[6];
            #pragma unroll
            for (int i=0;i<6;i++) rinv[i] = __fdividef(1.0f, Lm[i][i]);
            float wv[6], x[6];
            #pragma unroll
            for (int i=0;i<6;i++){
                float sr = rhssm[i];
                #pragma unroll
                for (int jj=0;jj<6;jj++) if (jj < i) sr -= Lm[i][jj]*wv[jj];
                wv[i] = sr * rinv[i];
            }
            #pragma unroll
            for (int i=5;i>=0;i--){
                float sr = wv[i];
                #pragma unroll
                for (int jj=0;jj<6;jj++) if (jj > i) sr -= Lm[jj][i]*x[jj];
                x[i] = sr * rinv[i];
            }
            #pragma unroll
            for (int i=0;i<6;i++) kout[e*6+i] = x[i];
        }
        __syncwarp();
    }
}

// ---------------- final RK4 combine ----------------
__global__ void stageFK(const float* __restrict__ obs, float* __restrict__ out){
    int e = blockIdx.x*blockDim.x + threadIdx.x;
    if (e >= BATCH) return;
    #pragma unroll
    for (int i=0;i<6;i++){
        float q  = obs[e*12 + i];
        float qd = obs[e*12 + 6 + i];
        float k1 = g_kqd[0][e*6+i];
        float k2 = g_kqd[1][e*6+i];
        float k3 = g_kqd[2][e*6+i];
        float k4 = g_kqd[3][e*6+i];
        float k1q = qd;
        float k2q = qd + 0.5f*DTc*k1;
        float k3q = qd + 0.5f*DTc*k2;
        float k4q = qd + DTc*k3;
        float qn  = q  + (DTc/6.0f)*(k1q + 2.f*k2q + 2.f*k3q + k4q);
        float qdn = qd + (DTc/6.0f)*(k1  + 2.f*k2  + 2.f*k3  + k4 );
        qn = fminf(fmaxf(qn, c_LOWER[i]), c_UPPER[i]);
        out[e*12 + i]     = qn;
        out[e*12 + 6 + i] = qdn;
    }
}

extern "C" void kernel_launch(void* const* d_in, const int* in_sizes, int n_in,
                              void* d_out, int out_size)
{
    const float* obs    = (const float*)d_in[0];
    const float* action = (const float*)d_in[1];
    const float* W1L = (const float*)d_in[2];  const float* b1L = (const float*)d_in[3];
    const float* W2L = (const float*)d_in[4];  const float* b2L = (const float*)d_in[5];
    const float* W3L = (const float*)d_in[6];  const float* b3L = (const float*)d_in[7];
    const float* W1V = (const float*)d_in[8];  const float* b1V = (const float*)d_in[9];
    const float* W2V = (const float*)d_in[10]; const float* b2V = (const float*)d_in[11];
    const float* W3V = (const float*)d_in[12];
    float* out = (float*)d_out;

    cudaFuncSetAttribute(stageBK, cudaFuncAttributeMaxDynamicSharedMemorySize, SMEM_BYTES);

    zeroMaskK<<<1, 32>>>();
    for (int st = 0; st < 4; st++){
        stageAK<<<BATCH/256, 256>>>(obs, st);
        stageBK<<<NBLK, TPB, SMEM_BYTES>>>(W1L,b1L,W2L,b2L,W3L,b3L,
                                           W1V,b1V,W2V,b2V,W3V, action, st);
    }
    stageFK<<<BATCH/256, 256>>>(obs, out);
}